// round 12
// baseline (speedup 1.0000x reference)
#include <cuda_runtime.h>
#include <cuda_bf16.h>
#include <cstddef>

#define N_NODES 100000
#define N_EDGES 1600000
#define C 64
#define CO2 40
#define EPSV 1e-5f

#define SCAN_CHUNK 1024
#define NB ((N_NODES + SCAN_CHUNK - 1) / SCAN_CHUNK)   // 98

// ---------------- scratch (__device__ globals) ----------------
__device__ int   g_is64;
__device__ int   g_deg[N_NODES];
__device__ int   g_rowptr[N_NODES + 1];
__device__ int   g_rowoff[N_NODES];
__device__ int   g_bsum[NB];
__device__ int   g_boff[NB];
__device__ int   g_csr[N_EDGES];
__device__ __align__(16) float g_mean[(size_t)N_NODES * C];
__device__ __align__(16) float g_h0[(size_t)N_NODES * C];
__device__ __align__(16) float g_h1[(size_t)N_NODES * C];
__device__ float g_sum[2][C];
__device__ float g_sq[2][C];
__device__ float g_bns[2][C];   // scale
__device__ float g_bnt[2][C];   // shift

// ---------------- dtype probe (warp-parallel, no serial load chain) ----------------
__global__ void k_detect(const int* __restrict__ ei) {
    int lane = threadIdx.x & 31;
    int nz = 0;
    #pragma unroll
    for (int i = 0; i < 4; i++)
        nz |= __ldg(&ei[2 * (lane * 4 + i) + 1]);
    unsigned any = __ballot_sync(0xFFFFFFFFu, nz != 0);
    if (lane == 0) g_is64 = (any == 0u);
}

// ---------------- init ----------------
__global__ void k_zero() {
    int i = blockIdx.x * blockDim.x + threadIdx.x;
    if (i < N_NODES) g_deg[i] = 0;
    if (i < C) {
        g_sum[0][i] = 0.f; g_sq[0][i] = 0.f;
        g_sum[1][i] = 0.f; g_sq[1][i] = 0.f;
    }
}

// ---------------- CSR build (edge_index: [2, E], dtype detected at runtime) ----------------
__global__ void k_count(const int* __restrict__ ei) {
    int e = blockIdx.x * blockDim.x + threadIdx.x;
    if (e >= N_EDGES) return;
    int dst = g_is64 ? ei[2 * (N_EDGES + e)] : ei[N_EDGES + e];
    if ((unsigned)dst < (unsigned)N_NODES) atomicAdd(&g_deg[dst], 1);
}

// phase 1: per-chunk exclusive scan (chunk = 1024), chunk total -> g_bsum
__global__ void __launch_bounds__(1024) k_scan_local() {
    __shared__ int warpTot[32];
    const int lane = threadIdx.x & 31;
    const int wid  = threadIdx.x >> 5;
    int i = blockIdx.x * SCAN_CHUNK + threadIdx.x;
    int v = (i < N_NODES) ? g_deg[i] : 0;
    int incl = v;
    #pragma unroll
    for (int o = 1; o < 32; o <<= 1) {
        int n = __shfl_up_sync(0xFFFFFFFFu, incl, o);
        if (lane >= o) incl += n;
    }
    if (lane == 31) warpTot[wid] = incl;
    __syncthreads();
    if (wid == 0) {
        int wincl = warpTot[lane];
        #pragma unroll
        for (int o = 1; o < 32; o <<= 1) {
            int n = __shfl_up_sync(0xFFFFFFFFu, wincl, o);
            if (lane >= o) wincl += n;
        }
        warpTot[lane] = wincl;
    }
    __syncthreads();
    int offset = (wid > 0 ? warpTot[wid - 1] : 0);
    if (i < N_NODES) g_rowptr[i] = offset + incl - v;   // chunk-local exclusive
    if (threadIdx.x == 0) g_bsum[blockIdx.x] = warpTot[31];
}

// phase 2: scan the NB chunk totals (1 block, 128 threads, Hillis-Steele)
__global__ void __launch_bounds__(128) k_scan_mid() {
    __shared__ int sh[128];
    int t = threadIdx.x;
    int v = (t < NB) ? g_bsum[t] : 0;
    sh[t] = v;
    __syncthreads();
    #pragma unroll
    for (int o = 1; o < 128; o <<= 1) {
        int n = (t >= o) ? sh[t - o] : 0;
        __syncthreads();
        sh[t] += n;
        __syncthreads();
    }
    int incl = sh[t];
    if (t < NB) g_boff[t] = incl - v;
    if (t == NB - 1) g_rowptr[N_NODES] = incl;
}

// phase 3: add chunk offsets
__global__ void __launch_bounds__(1024) k_scan_fix() {
    int i = blockIdx.x * SCAN_CHUNK + threadIdx.x;
    if (i < N_NODES) {
        int v = g_rowptr[i] + g_boff[blockIdx.x];
        g_rowptr[i] = v;
        g_rowoff[i] = v;
    }
}

__global__ void k_scatter(const int* __restrict__ ei) {
    int e = blockIdx.x * blockDim.x + threadIdx.x;
    if (e >= N_EDGES) return;
    int is64 = g_is64;
    int src = is64 ? ei[2 * e] : ei[e];
    int dst = is64 ? ei[2 * (N_EDGES + e)] : ei[N_EDGES + e];
    if ((unsigned)dst < (unsigned)N_NODES && (unsigned)src < (unsigned)N_NODES) {
        int pos = atomicAdd(&g_rowoff[dst], 1);
        g_csr[pos] = src;
    }
}

// ---------------- mean aggregation (warp per node, 2 channels per lane, 4-edge unroll) ----
// LAYER: 0 reads external x, 1 reads g_h0 (+BN0), 2 reads g_h1 (+BN1). Writes g_mean.
template <int LAYER>
__global__ void __launch_bounds__(256) k_agg(const float* __restrict__ xext) {
    int gw = (blockIdx.x * blockDim.x + threadIdx.x) >> 5;
    if (gw >= N_NODES) return;
    const float* __restrict__ h =
        (LAYER == 0) ? xext : (LAYER == 1 ? (const float*)g_h0 : (const float*)g_h1);
    const int lane = threadIdx.x & 31;
    const int c0 = lane * 2;
    float s0 = 1.f, s1 = 1.f, t0 = 0.f, t1 = 0.f;
    if (LAYER >= 1) {
        s0 = g_bns[LAYER - 1][c0]; s1 = g_bns[LAYER - 1][c0 + 1];
        t0 = g_bnt[LAYER - 1][c0]; t1 = g_bnt[LAYER - 1][c0 + 1];
    }
    const int start = g_rowptr[gw];
    const int end   = g_rowptr[gw + 1];
    float ax = 0.f, ay = 0.f;
    int k = start;
    for (; k + 4 <= end; k += 4) {
        int i0 = __ldg(&g_csr[k]);
        int i1 = __ldg(&g_csr[k + 1]);
        int i2 = __ldg(&g_csr[k + 2]);
        int i3 = __ldg(&g_csr[k + 3]);
        float2 v0 = __ldg(reinterpret_cast<const float2*>(&h[(size_t)i0 * C + c0]));
        float2 v1 = __ldg(reinterpret_cast<const float2*>(&h[(size_t)i1 * C + c0]));
        float2 v2 = __ldg(reinterpret_cast<const float2*>(&h[(size_t)i2 * C + c0]));
        float2 v3 = __ldg(reinterpret_cast<const float2*>(&h[(size_t)i3 * C + c0]));
        if (LAYER >= 1) {
            v0.x = fmaxf(fmaf(v0.x, s0, t0), 0.f); v0.y = fmaxf(fmaf(v0.y, s1, t1), 0.f);
            v1.x = fmaxf(fmaf(v1.x, s0, t0), 0.f); v1.y = fmaxf(fmaf(v1.y, s1, t1), 0.f);
            v2.x = fmaxf(fmaf(v2.x, s0, t0), 0.f); v2.y = fmaxf(fmaf(v2.y, s1, t1), 0.f);
            v3.x = fmaxf(fmaf(v3.x, s0, t0), 0.f); v3.y = fmaxf(fmaf(v3.y, s1, t1), 0.f);
        }
        ax += (v0.x + v1.x) + (v2.x + v3.x);
        ay += (v0.y + v1.y) + (v2.y + v3.y);
    }
    for (; k < end; ++k) {
        int i0 = __ldg(&g_csr[k]);
        float2 v = __ldg(reinterpret_cast<const float2*>(&h[(size_t)i0 * C + c0]));
        if (LAYER >= 1) {
            v.x = fmaxf(fmaf(v.x, s0, t0), 0.f);
            v.y = fmaxf(fmaf(v.y, s1, t1), 0.f);
        }
        ax += v.x; ay += v.y;
    }
    float d = fmaxf((float)(end - start), 1.f);
    float2 out; out.x = ax / d; out.y = ay / d;
    *reinterpret_cast<float2*>(&g_mean[(size_t)gw * C + c0]) = out;
}

// ---------------- fused dual GEMM: y = mean@Wl + act(x)@Wr + b ----------------
template <int CO, int LAYER>
__global__ void __launch_bounds__(256) k_gemm(const float* __restrict__ xext,
                                              const float* __restrict__ Wl,
                                              const float* __restrict__ Wr,
                                              const float* __restrict__ bias,
                                              float* __restrict__ yext) {
    __shared__ float sW[C * CO];
    __shared__ float sT[64 * (C + 1)];

    const float* __restrict__ xin =
        (LAYER == 0) ? xext : (LAYER == 1 ? (const float*)g_h0 : (const float*)g_h1);
    float* __restrict__ y =
        (LAYER == 2) ? yext : (LAYER == 0 ? (float*)g_h0 : (float*)g_h1);

    const int tid  = threadIdx.x;
    const int row0 = blockIdx.x * 64;

    // ---- pass 1: acc = bias + mean @ Wl ----
    for (int i = tid; i < C * CO; i += 256) sW[i] = Wl[i];
    for (int i = tid; i < 64 * C; i += 256) {
        int r = i >> 6, c = i & 63;
        int gr = row0 + r;
        sT[r * (C + 1) + c] = (gr < N_NODES) ? g_mean[(size_t)gr * C + c] : 0.f;
    }
    __syncthreads();

    const int r  = tid >> 2;
    const int jg = tid & 3;
    constexpr int NJ = CO / 4;
    float acc[NJ];
    #pragma unroll
    for (int i = 0; i < NJ; i++) acc[i] = __ldg(&bias[jg + 4 * i]);

    #pragma unroll 8
    for (int c = 0; c < C; c++) {
        float a = sT[r * (C + 1) + c];
        #pragma unroll
        for (int i = 0; i < NJ; i++)
            acc[i] = fmaf(a, sW[c * CO + jg + 4 * i], acc[i]);
    }
    __syncthreads();

    // ---- pass 2: acc += act(x) @ Wr ----
    for (int i = tid; i < C * CO; i += 256) sW[i] = Wr[i];
    for (int i = tid; i < 64 * C; i += 256) {
        int r2 = i >> 6, c = i & 63;
        int gr = row0 + r2;
        float xv = 0.f;
        if (gr < N_NODES) {
            xv = xin[(size_t)gr * C + c];
            if (LAYER >= 1)
                xv = fmaxf(fmaf(xv, g_bns[LAYER - 1][c], g_bnt[LAYER - 1][c]), 0.f);
        }
        sT[r2 * (C + 1) + c] = xv;
    }
    __syncthreads();

    #pragma unroll 8
    for (int c = 0; c < C; c++) {
        float xv = sT[r * (C + 1) + c];
        #pragma unroll
        for (int i = 0; i < NJ; i++)
            acc[i] = fmaf(xv, sW[c * CO + jg + 4 * i], acc[i]);
    }

    const int gr = row0 + r;
    if (gr < N_NODES) {
        #pragma unroll
        for (int i = 0; i < NJ; i++) y[(size_t)gr * CO + jg + 4 * i] = acc[i];
    }
}

// ---------------- batchnorm stats over pre-activation h ----------------
template <int WHICH>
__global__ void __launch_bounds__(256) k_stats() {
    const float* __restrict__ y = (WHICH == 0) ? (const float*)g_h0 : (const float*)g_h1;
    const int c = threadIdx.x & 63;
    const int rstart = blockIdx.x * 4 + (threadIdx.x >> 6);
    const int rstep = gridDim.x * 4;
    float s = 0.f, q = 0.f;
    for (int r = rstart; r < N_NODES; r += rstep) {
        float v = y[(size_t)r * C + c];
        s += v;
        q = fmaf(v, v, q);
    }
    __shared__ float shS[256], shQ[256];
    shS[threadIdx.x] = s; shQ[threadIdx.x] = q;
    __syncthreads();
    if (threadIdx.x < 64) {
        float ts = shS[threadIdx.x] + shS[threadIdx.x + 64] + shS[threadIdx.x + 128] + shS[threadIdx.x + 192];
        float tq = shQ[threadIdx.x] + shQ[threadIdx.x + 64] + shQ[threadIdx.x + 128] + shQ[threadIdx.x + 192];
        atomicAdd(&g_sum[WHICH][threadIdx.x], ts);
        atomicAdd(&g_sq[WHICH][threadIdx.x], tq);
    }
}

__global__ void k_finalize(const float* __restrict__ gamma,
                           const float* __restrict__ beta, int which) {
    int c = threadIdx.x;
    if (c < C) {
        float mu  = g_sum[which][c] * (1.f / N_NODES);
        float var = g_sq[which][c] * (1.f / N_NODES) - mu * mu;
        float sc  = gamma[c] * rsqrtf(var + EPSV);
        g_bns[which][c] = sc;
        g_bnt[which][c] = fmaf(-mu, sc, beta[c]);
    }
}

// ---------------- launch: kernel launches ONLY ----------------
extern "C" void kernel_launch(void* const* d_in, const int* in_sizes, int n_in,
                              void* d_out, int out_size) {
    const float* x   = (const float*)d_in[0];
    const int*   ei  = (const int*)d_in[1];   // dtype (int32 vs int64) detected on device
    const float* Wl0 = (const float*)d_in[2];
    const float* Wr0 = (const float*)d_in[3];
    const float* b0  = (const float*)d_in[4];
    const float* Wl1 = (const float*)d_in[5];
    const float* Wr1 = (const float*)d_in[6];
    const float* b1  = (const float*)d_in[7];
    const float* Wl2 = (const float*)d_in[8];
    const float* Wr2 = (const float*)d_in[9];
    const float* b2  = (const float*)d_in[10];
    const float* g0  = (const float*)d_in[11];
    const float* be0 = (const float*)d_in[12];
    const float* g1  = (const float*)d_in[13];
    const float* be1 = (const float*)d_in[14];
    float* out = (float*)d_out;

    const int gemmGrid = (N_NODES + 63) / 64;     // 1563
    const int aggGrid  = (N_NODES + 7) / 8;       // 12500 (8 warps/block)
    const int edgeGrid = (N_EDGES + 255) / 256;   // 6250

    k_detect<<<1, 32>>>(ei);
    k_zero<<<(N_NODES + 255) / 256, 256>>>();
    k_count<<<edgeGrid, 256>>>(ei);
    k_scan_local<<<NB, 1024>>>();
    k_scan_mid<<<1, 128>>>();
    k_scan_fix<<<NB, 1024>>>();
    k_scatter<<<edgeGrid, 256>>>(ei);

    // layer 0
    k_agg<0><<<aggGrid, 256>>>(x);
    k_gemm<64, 0><<<gemmGrid, 256>>>(x, Wl0, Wr0, b0, nullptr);
    k_stats<0><<<512, 256>>>();
    k_finalize<<<1, 64>>>(g0, be0, 0);

    // layer 1
    k_agg<1><<<aggGrid, 256>>>(nullptr);
    k_gemm<64, 1><<<gemmGrid, 256>>>(nullptr, Wl1, Wr1, b1, nullptr);
    k_stats<1><<<512, 256>>>();
    k_finalize<<<1, 64>>>(g1, be1, 1);

    // layer 2 -> output (no BN/ReLU after)
    k_agg<2><<<aggGrid, 256>>>(nullptr);
    k_gemm<CO2, 2><<<gemmGrid, 256>>>(nullptr, Wl2, Wr2, b2, out);
}

// round 16
// speedup vs baseline: 1.4987x; 1.4987x over previous
// R14 = R13 resubmission (R13 hit "GB300 container failed twice" infra error; kernel never ran).
// Experiment under test: parallel 3-phase scan + warp-parallel dtype probe (proven -88us/-33us)
// with k_agg reverted to the R10 single-edge software-pipelined loop (tests the MLP_p1
// multi-CTA-spread theory for the R12 regression).
#include <cuda_runtime.h>
#include <cuda_bf16.h>
#include <cstddef>

#define N_NODES 100000
#define N_EDGES 1600000
#define C 64
#define CO2 40
#define EPSV 1e-5f

#define SCAN_CHUNK 1024
#define NB ((N_NODES + SCAN_CHUNK - 1) / SCAN_CHUNK)   // 98

// ---------------- scratch (__device__ globals) ----------------
__device__ int   g_is64;
__device__ int   g_deg[N_NODES];
__device__ int   g_rowptr[N_NODES + 1];
__device__ int   g_rowoff[N_NODES];
__device__ int   g_bsum[NB];
__device__ int   g_boff[NB];
__device__ int   g_csr[N_EDGES];
__device__ __align__(16) float g_mean[(size_t)N_NODES * C];
__device__ __align__(16) float g_h0[(size_t)N_NODES * C];
__device__ __align__(16) float g_h1[(size_t)N_NODES * C];
__device__ float g_sum[2][C];
__device__ float g_sq[2][C];
__device__ float g_bns[2][C];   // scale
__device__ float g_bnt[2][C];   // shift

// ---------------- dtype probe (warp-parallel, no serial load chain) ----------------
__global__ void k_detect(const int* __restrict__ ei) {
    int lane = threadIdx.x & 31;
    int nz = 0;
    #pragma unroll
    for (int i = 0; i < 4; i++)
        nz |= __ldg(&ei[2 * (lane * 4 + i) + 1]);
    unsigned any = __ballot_sync(0xFFFFFFFFu, nz != 0);
    if (lane == 0) g_is64 = (any == 0u);
}

// ---------------- init ----------------
__global__ void k_zero() {
    int i = blockIdx.x * blockDim.x + threadIdx.x;
    if (i < N_NODES) g_deg[i] = 0;
    if (i < C) {
        g_sum[0][i] = 0.f; g_sq[0][i] = 0.f;
        g_sum[1][i] = 0.f; g_sq[1][i] = 0.f;
    }
}

// ---------------- CSR build (edge_index: [2, E], dtype detected at runtime) ----------------
__global__ void k_count(const int* __restrict__ ei) {
    int e = blockIdx.x * blockDim.x + threadIdx.x;
    if (e >= N_EDGES) return;
    int dst = g_is64 ? ei[2 * (N_EDGES + e)] : ei[N_EDGES + e];
    if ((unsigned)dst < (unsigned)N_NODES) atomicAdd(&g_deg[dst], 1);
}

// phase 1: per-chunk exclusive scan (chunk = 1024), chunk total -> g_bsum
__global__ void __launch_bounds__(1024) k_scan_local() {
    __shared__ int warpTot[32];
    const int lane = threadIdx.x & 31;
    const int wid  = threadIdx.x >> 5;
    int i = blockIdx.x * SCAN_CHUNK + threadIdx.x;
    int v = (i < N_NODES) ? g_deg[i] : 0;
    int incl = v;
    #pragma unroll
    for (int o = 1; o < 32; o <<= 1) {
        int n = __shfl_up_sync(0xFFFFFFFFu, incl, o);
        if (lane >= o) incl += n;
    }
    if (lane == 31) warpTot[wid] = incl;
    __syncthreads();
    if (wid == 0) {
        int wincl = warpTot[lane];
        #pragma unroll
        for (int o = 1; o < 32; o <<= 1) {
            int n = __shfl_up_sync(0xFFFFFFFFu, wincl, o);
            if (lane >= o) wincl += n;
        }
        warpTot[lane] = wincl;
    }
    __syncthreads();
    int offset = (wid > 0 ? warpTot[wid - 1] : 0);
    if (i < N_NODES) g_rowptr[i] = offset + incl - v;   // chunk-local exclusive
    if (threadIdx.x == 0) g_bsum[blockIdx.x] = warpTot[31];
}

// phase 2: scan the NB chunk totals (1 block, 128 threads, Hillis-Steele)
__global__ void __launch_bounds__(128) k_scan_mid() {
    __shared__ int sh[128];
    int t = threadIdx.x;
    int v = (t < NB) ? g_bsum[t] : 0;
    sh[t] = v;
    __syncthreads();
    #pragma unroll
    for (int o = 1; o < 128; o <<= 1) {
        int n = (t >= o) ? sh[t - o] : 0;
        __syncthreads();
        sh[t] += n;
        __syncthreads();
    }
    int incl = sh[t];
    if (t < NB) g_boff[t] = incl - v;
    if (t == NB - 1) g_rowptr[N_NODES] = incl;
}

// phase 3: add chunk offsets
__global__ void __launch_bounds__(1024) k_scan_fix() {
    int i = blockIdx.x * SCAN_CHUNK + threadIdx.x;
    if (i < N_NODES) {
        int v = g_rowptr[i] + g_boff[blockIdx.x];
        g_rowptr[i] = v;
        g_rowoff[i] = v;
    }
}

__global__ void k_scatter(const int* __restrict__ ei) {
    int e = blockIdx.x * blockDim.x + threadIdx.x;
    if (e >= N_EDGES) return;
    int is64 = g_is64;
    int src = is64 ? ei[2 * e] : ei[e];
    int dst = is64 ? ei[2 * (N_EDGES + e)] : ei[N_EDGES + e];
    if ((unsigned)dst < (unsigned)N_NODES && (unsigned)src < (unsigned)N_NODES) {
        int pos = atomicAdd(&g_rowoff[dst], 1);
        g_csr[pos] = src;
    }
}

// ---------------- mean aggregation (warp per node, 2 channels per lane) ----------------
// R10-proven inner loop: single-edge software pipeline (prefetch next index),
// plain float2 loads — keeps MLP_p1 low to avoid cross-CTA L1tex-queue spread.
// LAYER: 0 reads external x, 1 reads g_h0 (+BN0), 2 reads g_h1 (+BN1). Writes g_mean.
template <int LAYER>
__global__ void __launch_bounds__(256) k_agg(const float* __restrict__ xext) {
    int gw = (blockIdx.x * blockDim.x + threadIdx.x) >> 5;
    if (gw >= N_NODES) return;
    const float* __restrict__ h =
        (LAYER == 0) ? xext : (LAYER == 1 ? (const float*)g_h0 : (const float*)g_h1);
    const int lane = threadIdx.x & 31;
    const int c0 = lane * 2;
    float s0 = 1.f, s1 = 1.f, t0 = 0.f, t1 = 0.f;
    if (LAYER >= 1) {
        s0 = g_bns[LAYER - 1][c0]; s1 = g_bns[LAYER - 1][c0 + 1];
        t0 = g_bnt[LAYER - 1][c0]; t1 = g_bnt[LAYER - 1][c0 + 1];
    }
    const int start = g_rowptr[gw];
    const int end   = g_rowptr[gw + 1];
    float ax = 0.f, ay = 0.f;
    int k = start;
    int src = (k < end) ? __ldg(&g_csr[k]) : 0;
    while (k < end) {
        int nsrc = (k + 1 < end) ? __ldg(&g_csr[k + 1]) : 0;
        float2 v = *reinterpret_cast<const float2*>(&h[(size_t)src * C + c0]);
        if (LAYER >= 1) {
            v.x = fmaxf(fmaf(v.x, s0, t0), 0.f);
            v.y = fmaxf(fmaf(v.y, s1, t1), 0.f);
        }
        ax += v.x; ay += v.y;
        src = nsrc; ++k;
    }
    float d = fmaxf((float)(end - start), 1.f);
    float2 out; out.x = ax / d; out.y = ay / d;
    *reinterpret_cast<float2*>(&g_mean[(size_t)gw * C + c0]) = out;
}

// ---------------- fused dual GEMM: y = mean@Wl + act(x)@Wr + b ----------------
template <int CO, int LAYER>
__global__ void __launch_bounds__(256) k_gemm(const float* __restrict__ xext,
                                              const float* __restrict__ Wl,
                                              const float* __restrict__ Wr,
                                              const float* __restrict__ bias,
                                              float* __restrict__ yext) {
    __shared__ float sW[C * CO];
    __shared__ float sT[64 * (C + 1)];

    const float* __restrict__ xin =
        (LAYER == 0) ? xext : (LAYER == 1 ? (const float*)g_h0 : (const float*)g_h1);
    float* __restrict__ y =
        (LAYER == 2) ? yext : (LAYER == 0 ? (float*)g_h0 : (float*)g_h1);

    const int tid  = threadIdx.x;
    const int row0 = blockIdx.x * 64;

    // ---- pass 1: acc = bias + mean @ Wl ----
    for (int i = tid; i < C * CO; i += 256) sW[i] = Wl[i];
    for (int i = tid; i < 64 * C; i += 256) {
        int r = i >> 6, c = i & 63;
        int gr = row0 + r;
        sT[r * (C + 1) + c] = (gr < N_NODES) ? g_mean[(size_t)gr * C + c] : 0.f;
    }
    __syncthreads();

    const int r  = tid >> 2;
    const int jg = tid & 3;
    constexpr int NJ = CO / 4;
    float acc[NJ];
    #pragma unroll
    for (int i = 0; i < NJ; i++) acc[i] = __ldg(&bias[jg + 4 * i]);

    #pragma unroll 8
    for (int c = 0; c < C; c++) {
        float a = sT[r * (C + 1) + c];
        #pragma unroll
        for (int i = 0; i < NJ; i++)
            acc[i] = fmaf(a, sW[c * CO + jg + 4 * i], acc[i]);
    }
    __syncthreads();

    // ---- pass 2: acc += act(x) @ Wr ----
    for (int i = tid; i < C * CO; i += 256) sW[i] = Wr[i];
    for (int i = tid; i < 64 * C; i += 256) {
        int r2 = i >> 6, c = i & 63;
        int gr = row0 + r2;
        float xv = 0.f;
        if (gr < N_NODES) {
            xv = xin[(size_t)gr * C + c];
            if (LAYER >= 1)
                xv = fmaxf(fmaf(xv, g_bns[LAYER - 1][c], g_bnt[LAYER - 1][c]), 0.f);
        }
        sT[r2 * (C + 1) + c] = xv;
    }
    __syncthreads();

    #pragma unroll 8
    for (int c = 0; c < C; c++) {
        float xv = sT[r * (C + 1) + c];
        #pragma unroll
        for (int i = 0; i < NJ; i++)
            acc[i] = fmaf(xv, sW[c * CO + jg + 4 * i], acc[i]);
    }

    const int gr = row0 + r;
    if (gr < N_NODES) {
        #pragma unroll
        for (int i = 0; i < NJ; i++) y[(size_t)gr * CO + jg + 4 * i] = acc[i];
    }
}

// ---------------- batchnorm stats over pre-activation h ----------------
template <int WHICH>
__global__ void __launch_bounds__(256) k_stats() {
    const float* __restrict__ y = (WHICH == 0) ? (const float*)g_h0 : (const float*)g_h1;
    const int c = threadIdx.x & 63;
    const int rstart = blockIdx.x * 4 + (threadIdx.x >> 6);
    const int rstep = gridDim.x * 4;
    float s = 0.f, q = 0.f;
    for (int r = rstart; r < N_NODES; r += rstep) {
        float v = y[(size_t)r * C + c];
        s += v;
        q = fmaf(v, v, q);
    }
    __shared__ float shS[256], shQ[256];
    shS[threadIdx.x] = s; shQ[threadIdx.x] = q;
    __syncthreads();
    if (threadIdx.x < 64) {
        float ts = shS[threadIdx.x] + shS[threadIdx.x + 64] + shS[threadIdx.x + 128] + shS[threadIdx.x + 192];
        float tq = shQ[threadIdx.x] + shQ[threadIdx.x + 64] + shQ[threadIdx.x + 128] + shQ[threadIdx.x + 192];
        atomicAdd(&g_sum[WHICH][threadIdx.x], ts);
        atomicAdd(&g_sq[WHICH][threadIdx.x], tq);
    }
}

__global__ void k_finalize(const float* __restrict__ gamma,
                           const float* __restrict__ beta, int which) {
    int c = threadIdx.x;
    if (c < C) {
        float mu  = g_sum[which][c] * (1.f / N_NODES);
        float var = g_sq[which][c] * (1.f / N_NODES) - mu * mu;
        float sc  = gamma[c] * rsqrtf(var + EPSV);
        g_bns[which][c] = sc;
        g_bnt[which][c] = fmaf(-mu, sc, beta[c]);
    }
}

// ---------------- launch: kernel launches ONLY ----------------
extern "C" void kernel_launch(void* const* d_in, const int* in_sizes, int n_in,
                              void* d_out, int out_size) {
    const float* x   = (const float*)d_in[0];
    const int*   ei  = (const int*)d_in[1];   // dtype (int32 vs int64) detected on device
    const float* Wl0 = (const float*)d_in[2];
    const float* Wr0 = (const float*)d_in[3];
    const float* b0  = (const float*)d_in[4];
    const float* Wl1 = (const float*)d_in[5];
    const float* Wr1 = (const float*)d_in[6];
    const float* b1  = (const float*)d_in[7];
    const float* Wl2 = (const float*)d_in[8];
    const float* Wr2 = (const float*)d_in[9];
    const float* b2  = (const float*)d_in[10];
    const float* g0  = (const float*)d_in[11];
    const float* be0 = (const float*)d_in[12];
    const float* g1  = (const float*)d_in[13];
    const float* be1 = (const float*)d_in[14];
    float* out = (float*)d_out;

    const int gemmGrid = (N_NODES + 63) / 64;     // 1563
    const int aggGrid  = (N_NODES + 7) / 8;       // 12500 (8 warps/block)
    const int edgeGrid = (N_EDGES + 255) / 256;   // 6250

    k_detect<<<1, 32>>>(ei);
    k_zero<<<(N_NODES + 255) / 256, 256>>>();
    k_count<<<edgeGrid, 256>>>(ei);
    k_scan_local<<<NB, 1024>>>();
    k_scan_mid<<<1, 128>>>();
    k_scan_fix<<<NB, 1024>>>();
    k_scatter<<<edgeGrid, 256>>>(ei);

    // layer 0
    k_agg<0><<<aggGrid, 256>>>(x);
    k_gemm<64, 0><<<gemmGrid, 256>>>(x, Wl0, Wr0, b0, nullptr);
    k_stats<0><<<512, 256>>>();
    k_finalize<<<1, 64>>>(g0, be0, 0);

    // layer 1
    k_agg<1><<<aggGrid, 256>>>(nullptr);
    k_gemm<64, 1><<<gemmGrid, 256>>>(nullptr, Wl1, Wr1, b1, nullptr);
    k_stats<1><<<512, 256>>>();
    k_finalize<<<1, 64>>>(g1, be1, 1);

    // layer 2 -> output (no BN/ReLU after)
    k_agg<2><<<aggGrid, 256>>>(nullptr);
    k_gemm<CO2, 2><<<gemmGrid, 256>>>(nullptr, Wl2, Wr2, b2, out);
}